// round 1
// baseline (speedup 1.0000x reference)
#include <cuda_runtime.h>

#define BATCH 4
#define TT    1024
#define DD    1024
#define HH    8
#define DKK   128
#define PP    2047
#define MHS   (BATCH*TT)

// ---------------- scratch (device globals: no allocations allowed) ----------
__device__ float g_qu[BATCH*HH*TT*DKK];          // 16 MB  (B,H,T,DK)
__device__ float g_qv[BATCH*HH*TT*DKK];          // 16 MB
__device__ float g_k [BATCH*HH*TT*DKK];          // 16 MB
__device__ float g_v [BATCH*HH*TT*DKK];          // 16 MB
__device__ float g_p [HH*PP*DKK];                // 8 MB   (H,P,DK)
__device__ float g_scores[(size_t)BATCH*HH*TT*TT]; // 128 MB (B,H,T,T)
__device__ float g_o [BATCH*TT*DD];              // 16 MB  (B,T,D)

// ---------------- shared NT mainloop: C = A(MxK) * B(NxK)^T, 64x64 tile -----
// 256 threads, 4x4 microtile per thread, BK=16.
__device__ __forceinline__ void nt_mainloop(const float* __restrict__ A,
                                            const float* __restrict__ B,
                                            int M, int N, int K,
                                            int row0, int col0,
                                            float acc[4][4])
{
    __shared__ float As[16][64];
    __shared__ float Bs[16][64];
    const int tid = threadIdx.x;
    const int tx  = tid & 15, ty = tid >> 4;
    const int lr  = tid >> 2;          // 0..63  (row within tile)
    const int lc  = (tid & 3) << 2;    // 0,4,8,12 (k offset, float4)

    for (int k0 = 0; k0 < K; k0 += 16) {
        float4 a4 = {0.f,0.f,0.f,0.f}, b4 = {0.f,0.f,0.f,0.f};
        int ar = row0 + lr;
        if (ar < M) a4 = *reinterpret_cast<const float4*>(&A[(size_t)ar*K + k0 + lc]);
        int br = col0 + lr;
        if (br < N) b4 = *reinterpret_cast<const float4*>(&B[(size_t)br*K + k0 + lc]);
        As[lc+0][lr] = a4.x; As[lc+1][lr] = a4.y; As[lc+2][lr] = a4.z; As[lc+3][lr] = a4.w;
        Bs[lc+0][lr] = b4.x; Bs[lc+1][lr] = b4.y; Bs[lc+2][lr] = b4.z; Bs[lc+3][lr] = b4.w;
        __syncthreads();
        #pragma unroll
        for (int kk = 0; kk < 16; kk++) {
            float4 av = *reinterpret_cast<const float4*>(&As[kk][ty << 2]);
            float4 bv = *reinterpret_cast<const float4*>(&Bs[kk][tx << 2]);
            float ar_[4] = {av.x, av.y, av.z, av.w};
            float br_[4] = {bv.x, bv.y, bv.z, bv.w};
            #pragma unroll
            for (int i = 0; i < 4; i++)
                #pragma unroll
                for (int j = 0; j < 4; j++)
                    acc[i][j] += ar_[i] * br_[j];
        }
        __syncthreads();
    }
}

// ---------------- Q/K/V projection: hs(4096x1024) @ W^T, fused bias adds ----
__global__ void k_qkv(const float* __restrict__ hs,
                      const float* __restrict__ Wq,
                      const float* __restrict__ Wk,
                      const float* __restrict__ Wv,
                      const float* __restrict__ bu,
                      const float* __restrict__ bv)
{
    const float* W = (blockIdx.z == 0) ? Wq : ((blockIdx.z == 1) ? Wk : Wv);
    const int row0 = blockIdx.y * 64, col0 = blockIdx.x * 64;
    float acc[4][4] = {};
    nt_mainloop(hs, W, MHS, DD, DD, row0, col0, acc);
    const int tx = threadIdx.x & 15, ty = threadIdx.x >> 4;
    #pragma unroll
    for (int i = 0; i < 4; i++) {
        int m = row0 + (ty << 2) + i;
        int b = m >> 10, t = m & 1023;
        #pragma unroll
        for (int j = 0; j < 4; j++) {
            int n = col0 + (tx << 2) + j;
            int h = n >> 7, d = n & 127;
            size_t idx = ((size_t)(b * HH + h) * TT + t) * DKK + d;
            float a = acc[i][j];
            if (blockIdx.z == 0) {
                g_qu[idx] = a + bu[h * DKK + d];
                g_qv[idx] = a + bv[h * DKK + d];
            } else if (blockIdx.z == 1) {
                g_k[idx] = a;
            } else {
                g_v[idx] = a;
            }
        }
    }
}

// ---------------- P projection: pos_emb(2047x1024) @ Wp^T -> (H,P,DK) -------
__global__ void k_p(const float* __restrict__ pe, const float* __restrict__ Wp)
{
    const int row0 = blockIdx.y * 64, col0 = blockIdx.x * 64;
    float acc[4][4] = {};
    nt_mainloop(pe, Wp, PP, DD, DD, row0, col0, acc);
    const int tx = threadIdx.x & 15, ty = threadIdx.x >> 4;
    #pragma unroll
    for (int i = 0; i < 4; i++) {
        int m = row0 + (ty << 2) + i;
        if (m >= PP) continue;
        #pragma unroll
        for (int j = 0; j < 4; j++) {
            int n = col0 + (tx << 2) + j;
            int h = n >> 7, d = n & 127;
            g_p[((size_t)h * PP + m) * DKK + d] = acc[i][j];
        }
    }
}

// ---------------- AC: scores = qu @ k^T per (b,h) ---------------------------
__global__ void k_ac()
{
    const int bh = blockIdx.z;
    const float* A  = g_qu + (size_t)bh * TT * DKK;
    const float* Bm = g_k  + (size_t)bh * TT * DKK;
    float* C = g_scores + (size_t)bh * TT * TT;
    const int row0 = blockIdx.y * 64, col0 = blockIdx.x * 64;
    float acc[4][4] = {};
    nt_mainloop(A, Bm, TT, TT, DKK, row0, col0, acc);
    const int tx = threadIdx.x & 15, ty = threadIdx.x >> 4;
    #pragma unroll
    for (int i = 0; i < 4; i++) {
        int m = row0 + (ty << 2) + i;
        #pragma unroll
        for (int j = 0; j < 4; j++) {
            int n = col0 + (tx << 2) + j;
            C[(size_t)m * TT + n] = acc[i][j];
        }
    }
}

// ---------------- BD: scores[m, n+m-1023] += qv @ p^T (rel-shift fused) -----
__global__ void k_bd()
{
    const int bh = blockIdx.z, h = bh & 7;
    const int row0 = blockIdx.y * 64, col0 = blockIdx.x * 64;
    // tile entirely out of the shifted window? (k = n + m - 1023, need 0<=k<T)
    if (row0 + col0 + 126 < 1023 || row0 + col0 > 2046) return;
    const float* A  = g_qv + (size_t)bh * TT * DKK;
    const float* Bm = g_p  + (size_t)h * PP * DKK;
    float* C = g_scores + (size_t)bh * TT * TT;
    float acc[4][4] = {};
    nt_mainloop(A, Bm, TT, PP, DKK, row0, col0, acc);
    const int tx = threadIdx.x & 15, ty = threadIdx.x >> 4;
    #pragma unroll
    for (int i = 0; i < 4; i++) {
        int m = row0 + (ty << 2) + i;
        #pragma unroll
        for (int j = 0; j < 4; j++) {
            int n = col0 + (tx << 2) + j;
            if (n < PP) {
                int k = n + m - 1023;
                if (k >= 0 && k < TT)
                    C[(size_t)m * TT + k] += acc[i][j];
            }
        }
    }
}

// ---------------- softmax over each length-1024 row (with 1/sqrt(dk)) -------
__global__ void k_softmax()
{
    float* r = g_scores + (size_t)blockIdx.x * TT;
    const int tid = threadIdx.x;                 // 256 threads, float4 each
    float4 v = reinterpret_cast<float4*>(r)[tid];
    const float s = 0.08838834764831845f;        // 1/sqrt(128)
    v.x *= s; v.y *= s; v.z *= s; v.w *= s;

    __shared__ float redm[8];
    __shared__ float reds[8];

    float m = fmaxf(fmaxf(v.x, v.y), fmaxf(v.z, v.w));
    #pragma unroll
    for (int o = 16; o > 0; o >>= 1) m = fmaxf(m, __shfl_xor_sync(~0u, m, o));
    if ((tid & 31) == 0) redm[tid >> 5] = m;
    __syncthreads();
    m = redm[0];
    #pragma unroll
    for (int w = 1; w < 8; w++) m = fmaxf(m, redm[w]);

    float4 e;
    e.x = __expf(v.x - m); e.y = __expf(v.y - m);
    e.z = __expf(v.z - m); e.w = __expf(v.w - m);
    float sum = e.x + e.y + e.z + e.w;
    #pragma unroll
    for (int o = 16; o > 0; o >>= 1) sum += __shfl_xor_sync(~0u, sum, o);
    if ((tid & 31) == 0) reds[tid >> 5] = sum;
    __syncthreads();
    sum = reds[0];
    #pragma unroll
    for (int w = 1; w < 8; w++) sum += reds[w];

    float inv = __frcp_rn(sum);
    e.x *= inv; e.y *= inv; e.z *= inv; e.w *= inv;
    reinterpret_cast<float4*>(r)[tid] = e;
}

// ---------------- AV: o = attn(1024x1024) @ v(1024x128) per (b,h), NN -------
__global__ void k_av()
{
    const int bh = blockIdx.z, b = bh >> 3, h = bh & 7;
    const float* A  = g_scores + (size_t)bh * TT * TT;
    const float* Bm = g_v      + (size_t)bh * TT * DKK;
    const int row0 = blockIdx.y * 64, col0 = blockIdx.x * 64;

    __shared__ float As[16][64];
    __shared__ float Bs[16][64];
    const int tid = threadIdx.x;
    const int tx = tid & 15, ty = tid >> 4;
    const int lr = tid >> 2, lc = (tid & 3) << 2;    // A tile: 64 rows x 16 k
    const int br_ = tid >> 4, bc = (tid & 15) << 2;  // B tile: 16 k x 64 n
    float acc[4][4] = {};

    for (int k0 = 0; k0 < TT; k0 += 16) {
        float4 a4 = *reinterpret_cast<const float4*>(&A[(size_t)(row0 + lr) * TT + k0 + lc]);
        As[lc+0][lr] = a4.x; As[lc+1][lr] = a4.y; As[lc+2][lr] = a4.z; As[lc+3][lr] = a4.w;
        float4 b4 = *reinterpret_cast<const float4*>(&Bm[(size_t)(k0 + br_) * DKK + col0 + bc]);
        *reinterpret_cast<float4*>(&Bs[br_][bc]) = b4;
        __syncthreads();
        #pragma unroll
        for (int kk = 0; kk < 16; kk++) {
            float4 av = *reinterpret_cast<const float4*>(&As[kk][ty << 2]);
            float4 bv = *reinterpret_cast<const float4*>(&Bs[kk][tx << 2]);
            float ar_[4] = {av.x, av.y, av.z, av.w};
            float br2[4] = {bv.x, bv.y, bv.z, bv.w};
            #pragma unroll
            for (int i = 0; i < 4; i++)
                #pragma unroll
                for (int j = 0; j < 4; j++)
                    acc[i][j] += ar_[i] * br2[j];
        }
        __syncthreads();
    }
    #pragma unroll
    for (int i = 0; i < 4; i++) {
        int m = row0 + (ty << 2) + i;
        #pragma unroll
        for (int j = 0; j < 4; j++) {
            int n = col0 + (tx << 2) + j;
            g_o[(((size_t)b * TT + m) * HH + h) * DKK + n] = acc[i][j];
        }
    }
}

// ---------------- output projection: o(4096x1024) @ Wo^T -> d_out -----------
__global__ void k_out(const float* __restrict__ Wo, float* __restrict__ out)
{
    const int row0 = blockIdx.y * 64, col0 = blockIdx.x * 64;
    float acc[4][4] = {};
    nt_mainloop(g_o, Wo, MHS, DD, DD, row0, col0, acc);
    const int tx = threadIdx.x & 15, ty = threadIdx.x >> 4;
    #pragma unroll
    for (int i = 0; i < 4; i++) {
        int m = row0 + (ty << 2) + i;
        #pragma unroll
        for (int j = 0; j < 4; j++) {
            int n = col0 + (tx << 2) + j;
            out[(size_t)m * DD + n] = acc[i][j];
        }
    }
}

// ---------------- launch ----------------------------------------------------
extern "C" void kernel_launch(void* const* d_in, const int* in_sizes, int n_in,
                              void* d_out, int out_size)
{
    const float* hs = (const float*)d_in[0];
    const float* pe = (const float*)d_in[1];
    const float* Wq = (const float*)d_in[2];
    const float* Wk = (const float*)d_in[3];
    const float* Wv = (const float*)d_in[4];
    const float* Wo = (const float*)d_in[5];
    const float* Wp = (const float*)d_in[6];
    const float* bu = (const float*)d_in[7];
    const float* bv = (const float*)d_in[8];
    float* out = (float*)d_out;

    k_qkv<<<dim3(16, 64, 3), 256>>>(hs, Wq, Wk, Wv, bu, bv);
    k_p  <<<dim3(16, 32), 256>>>(pe, Wp);
    k_ac <<<dim3(16, 16, BATCH * HH), 256>>>();
    k_bd <<<dim3(32, 16, BATCH * HH), 256>>>();
    k_softmax<<<BATCH * HH * TT, 256>>>();
    k_av <<<dim3(2, 16, BATCH * HH), 256>>>();
    k_out<<<dim3(16, 64), 256>>>(Wo, out);
}